// round 3
// baseline (speedup 1.0000x reference)
#include <cuda_runtime.h>
#include <math.h>

#define BB 4
#define CC 128
#define NNp 4096
#define TW 132
typedef unsigned long long ull;

__device__ float g_x1[BB*CC*NNp];
__device__ float g_xf[BB*CC*NNp];
__device__ float g_sq[BB*NNp];
__device__ int   g_idx[BB*NNp*9];
__device__ float g_PC[4*BB*NNp*CC];   // [slot][b][n][o]
__device__ float g_h[BB*NNp*3*CC];    // [b][n][j][o]
__device__ float g_W4[4*CC*CC];
__device__ float g_Wl2[CC*3*CC];
__device__ float g_g0[BB*CC];
__device__ float g_g2[BB*CC];

__device__ __forceinline__ ull pack2(float a){
    ull r; unsigned ai=__float_as_uint(a);
    asm("mov.b64 %0, {%1, %2};" : "=l"(r) : "r"(ai), "r"(ai));
    return r;
}
__device__ __forceinline__ void fma2(ull &d, ull a, ull b){
    asm("fma.rn.f32x2 %0, %1, %2, %0;" : "+l"(d) : "l"(a), "l"(b));
}
__device__ __forceinline__ float2 unp(ull v){ union{ull u; float2 f;}c; c.u=v; return c.f; }

__device__ __forceinline__ void micro_step(const float* As, const float* Bs,
                                           int k, int r0, int c0, ull acc[8][4]){
    const float* ar = As + k*TW; const float* br = Bs + k*TW;
    float4 a0 = *(const float4*)(ar+r0);
    float4 a1 = *(const float4*)(ar+r0+64);
    ulonglong2 b0 = *(const ulonglong2*)(br+c0);
    ulonglong2 b1 = *(const ulonglong2*)(br+c0+64);
    ull av[8]={pack2(a0.x),pack2(a0.y),pack2(a0.z),pack2(a0.w),
               pack2(a1.x),pack2(a1.y),pack2(a1.z),pack2(a1.w)};
    ull bv[4]={b0.x,b0.y,b1.x,b1.y};
#pragma unroll
    for (int i=0;i<8;i++)
#pragma unroll
        for (int j=0;j<4;j++) fma2(acc[i][j], av[i], bv[j]);
}

// ---- weight prep: W4 (edge-conv factorization) + Wl2 flatten ----
__global__ void prep_kernel(const float* __restrict__ wl1, const float* __restrict__ wl2){
    for (int i = blockIdx.x*256 + threadIdx.x; i < 4*CC*CC; i += gridDim.x*256){
        int slot=i>>14, rem=i&16383, o=rem>>7, c=rem&127;
        float v;
        if (slot==0){
            v=0.f;
#pragma unroll
            for (int w=0;w<3;w++) v += wl1[(o*256+c)*3+w] + wl1[(o*256+128+c)*3+w];
        } else v = wl1[(o*256+128+c)*3+(slot-1)];
        g_W4[i]=v;
    }
    for (int i = blockIdx.x*256 + threadIdx.x; i < CC*3*CC; i += gridDim.x*256){
        int p=i/384, k=i%384, w=k>>7, o=k&127;
        g_Wl2[i] = wl2[(p*128+o)*3+w];
    }
}

// ---- pointwise conv: out[b][o][n] = relu(s*(W.x+b)+t) ----
__global__ void __launch_bounds__(256) pw_gemm(const float* __restrict__ X,
        const float* __restrict__ W, const float* __restrict__ bias,
        const float* __restrict__ sc, const float* __restrict__ tr_,
        float* __restrict__ out){
    __shared__ float As[16*TW], Bs[16*TW];
    int b=blockIdx.y, n0=blockIdx.x*128, tid=threadIdx.x;
    const float* Xb = X + (size_t)b*CC*NNp;
    int tr=tid>>4, tc=tid&15, r0=tr*4, c0=tc*4;
    ull acc[8][4];
#pragma unroll
    for(int i=0;i<8;i++)
#pragma unroll
        for(int j=0;j<4;j++) acc[i][j]=0ULL;
    for (int kk=0; kk<128; kk+=16){
        for (int i=tid;i<512;i+=256){             // W[o][c] -> As[c][o]
            int m=i>>2, k4=(i&3)*4;
            float4 v = *(const float4*)(W + m*128 + kk + k4);
            As[(k4+0)*TW+m]=v.x; As[(k4+1)*TW+m]=v.y; As[(k4+2)*TW+m]=v.z; As[(k4+3)*TW+m]=v.w;
        }
        for (int i=tid;i<512;i+=256){             // X[c][n] -> Bs[c][n]
            int k=i>>5, n4=(i&31)*4;
            *(float4*)&Bs[k*TW+n4] = *(const float4*)(Xb + (size_t)(kk+k)*NNp + n0 + n4);
        }
        __syncthreads();
#pragma unroll
        for (int k=0;k<16;k++) micro_step(As,Bs,k,r0,c0,acc);
        __syncthreads();
    }
#pragma unroll
    for (int i=0;i<8;i++){
        int row = (i<4)? r0+i : r0+60+i;
        float bb=bias[row], ss=sc[row], tt=tr_[row];
        float* orow = out + ((size_t)b*CC+row)*NNp + n0;
#pragma unroll
        for (int j=0;j<4;j++){
            int cj = (j<2)? c0+2*j : c0+60+2*j;
            float2 v=unp(acc[i][j]);
            float2 o; o.x=fmaxf(ss*(v.x+bb)+tt,0.f); o.y=fmaxf(ss*(v.y+bb)+tt,0.f);
            *(float2*)(orow+cj)=o;
        }
    }
}

__global__ void sq_kernel(const float* __restrict__ XF, float* __restrict__ SQ){
    int n=blockIdx.x*256+threadIdx.x, b=blockIdx.y;
    const float* p = XF + (size_t)b*CC*NNp + n;
    float s=0.f;
#pragma unroll 8
    for (int c=0;c<128;c++){ float v=p[(size_t)c*NNp]; s+=v*v; }
    SQ[b*NNp+n]=s;
}

// ---- fused Gram + top-9 KNN ----
extern __shared__ float knn_sm[];
__global__ void __launch_bounds__(256,1) knn_kernel(const float* __restrict__ XF,
        const float* __restrict__ SQ, int* __restrict__ IDX){
    float* Qs = knn_sm;                 // 128*TW
    float* Cs = knn_sm + 128*TW;        // 128*TW (reused as key tile [c][r])
    float* sqc = knn_sm + 2*128*TW;     // 128
    int b=blockIdx.y, q0=blockIdx.x*128, tid=threadIdx.x;
    const float* Xb = XF + (size_t)b*CC*NNp;
    for (int i=tid;i<128*32;i+=256){
        int k=i>>5, n4=(i&31)*4;
        *(float4*)&Qs[k*TW+n4] = *(const float4*)(Xb + (size_t)k*NNp + q0 + n4);
    }
    int tr=tid>>4, tc=tid&15, r0=tr*4, c0=tc*4;
    int rq=tid&127, half=tid>>7;
    const float NEGINF = __int_as_float(0xff800000);
    float tv[9]; int ti[9];
#pragma unroll
    for (int k=0;k<9;k++){ tv[k]=NEGINF; ti[k]=0x7fffffff; }

    for (int ct=0; ct<32; ct++){
        int cb=ct*128;
        __syncthreads();
        for (int i=tid;i<128*32;i+=256){
            int k=i>>5, n4=(i&31)*4;
            *(float4*)&Cs[k*TW+n4] = *(const float4*)(Xb + (size_t)k*NNp + cb + n4);
        }
        if (tid<32) *(float4*)&sqc[tid*4] = *(const float4*)(SQ + (size_t)b*NNp + cb + tid*4);
        __syncthreads();
        ull acc[8][4];
#pragma unroll
        for(int i=0;i<8;i++)
#pragma unroll
            for(int j=0;j<4;j++) acc[i][j]=0ULL;
#pragma unroll 4
        for (int k=0;k<128;k++) micro_step(Qs,Cs,k,r0,c0,acc);
        __syncthreads();
        // stage keys transposed: Cs[c*128+r] = 2*dot - sq_c
#pragma unroll
        for (int i=0;i<8;i++){
            int r=(i<4)? r0+i : r0+60+i;
#pragma unroll
            for (int j=0;j<4;j++){
                int cj=(j<2)? c0+2*j : c0+60+2*j;
                float2 v=unp(acc[i][j]);
                Cs[cj*128+r]     = 2.f*v.x - sqc[cj];
                Cs[(cj+1)*128+r] = 2.f*v.y - sqc[cj+1];
            }
        }
        __syncthreads();
        int cbase=half*64;
        for (int cc=0;cc<64;cc++){
            int c=cbase+cc;
            float v=Cs[c*128+rq];
            int jg=cb+c;
            if (v>tv[8] || (v==tv[8] && jg<ti[8])){
                tv[8]=v; ti[8]=jg;
#pragma unroll
                for (int p=8;p>0;--p){
                    bool sw=(tv[p]>tv[p-1])||(tv[p]==tv[p-1]&&ti[p]<ti[p-1]);
                    if (sw){ float fv=tv[p];tv[p]=tv[p-1];tv[p-1]=fv;
                             int iv=ti[p];ti[p]=ti[p-1];ti[p-1]=iv; }
                }
            }
        }
    }
    __syncthreads();
    float* Pv=Qs; int* Pi=(int*)(Qs+128*9);
    if (half==1){
#pragma unroll
        for (int k=0;k<9;k++){ Pv[rq*9+k]=tv[k]; Pi[rq*9+k]=ti[k]; }
    }
    __syncthreads();
    if (half==0){
        int pa=0, pb=0, res[9];
#pragma unroll
        for (int k=0;k<9;k++){
            float vb=Pv[rq*9+pb]; int jb=Pi[rq*9+pb];
            float va=tv[pa];      int ja=ti[pa];
            bool ta=(va>vb)||(va==vb&&ja<jb);
            if (ta){ res[k]=ja; pa++; } else { res[k]=jb; pb++; }
        }
        int* dst = IDX + ((size_t)b*NNp + q0 + rq)*9;
#pragma unroll
        for (int k=0;k<9;k++) dst[k]=res[k];
    }
}

// ---- per-tap GEMMs: out[slot][b][n][o] ----
__global__ void __launch_bounds__(256) pc_gemm(const float* __restrict__ X,
        const float* __restrict__ W4, float* __restrict__ out){
    __shared__ float As[16*TW], Bs[16*TW];
    int slot=blockIdx.z, b=blockIdx.y, n0=blockIdx.x*128, tid=threadIdx.x;
    const float* Xb = X + (size_t)b*CC*NNp;
    const float* Wd = W4 + (size_t)slot*CC*CC;
    int tr=tid>>4, tc=tid&15, r0=tr*4, c0=tc*4;
    ull acc[8][4];
#pragma unroll
    for(int i=0;i<8;i++)
#pragma unroll
        for(int j=0;j<4;j++) acc[i][j]=0ULL;
    for (int kk=0; kk<128; kk+=16){
        for (int i=tid;i<512;i+=256){             // rows = n
            int k=i>>5, n4=(i&31)*4;
            *(float4*)&As[k*TW+n4] = *(const float4*)(Xb + (size_t)(kk+k)*NNp + n0 + n4);
        }
        for (int i=tid;i<512;i+=256){             // cols = o
            int m=i>>2, k4=(i&3)*4;
            float4 v = *(const float4*)(Wd + m*128 + kk + k4);
            Bs[(k4+0)*TW+m]=v.x; Bs[(k4+1)*TW+m]=v.y; Bs[(k4+2)*TW+m]=v.z; Bs[(k4+3)*TW+m]=v.w;
        }
        __syncthreads();
#pragma unroll
        for (int k=0;k<16;k++) micro_step(As,Bs,k,r0,c0,acc);
        __syncthreads();
    }
    float* obase = out + (((size_t)slot*BB+b)*NNp + n0)*128;
#pragma unroll
    for (int i=0;i<8;i++){
        int row=(i<4)? r0+i : r0+60+i;            // n-local
#pragma unroll
        for (int j=0;j<4;j++){
            int cj=(j<2)? c0+2*j : c0+60+2*j;     // o
            *(float2*)(obase + (size_t)row*128 + cj) = unp(acc[i][j]);
        }
    }
}

// ---- gather + edge-conv epilogue ----
__global__ void __launch_bounds__(256) gather_kernel(const float* __restrict__ PC,
        const int* __restrict__ IDX, const float* __restrict__ b_l1,
        const float* __restrict__ s_l1, const float* __restrict__ t_l1,
        float* __restrict__ H){
    int b=blockIdx.y;
    int o=threadIdx.x&127, sub=threadIdx.x>>7;
    float bb=b_l1[o], ss=s_l1[o], tt=t_l1[o];
    const float* P0 = PC + ((size_t)0*BB+b)*NNp*128;
    const float* P1 = PC + ((size_t)1*BB+b)*NNp*128;
    const float* P2 = PC + ((size_t)2*BB+b)*NNp*128;
    const float* P3 = PC + ((size_t)3*BB+b)*NNp*128;
    for (int it=0; it<4; it++){
        int n = blockIdx.x*8 + it*2 + sub;
        const int* id = IDX + ((size_t)b*NNp+n)*9;
        float c0v = P0[(size_t)n*128+o];
#pragma unroll
        for (int j=0;j<3;j++){
            int i0=id[3*j], i1=id[3*j+1], i2=id[3*j+2];
            float v = c0v - P1[(size_t)i0*128+o] - P2[(size_t)i1*128+o] - P3[(size_t)i2*128+o];
            H[(((size_t)b*NNp+n)*3+j)*128+o] = fmaxf(ss*(v+bb)+tt,0.f);
        }
    }
}

// ---- global branch ----
__global__ void mean_kernel(const float* __restrict__ x1, float* __restrict__ g0){
    int c=blockIdx.x, b=blockIdx.y;
    const float* p = x1 + ((size_t)b*CC+c)*NNp;
    float s=0.f;
    for (int i=threadIdx.x;i<NNp;i+=256) s+=p[i];
    __shared__ float sm[8];
    for (int o=16;o;o>>=1) s+=__shfl_down_sync(~0u,s,o);
    if ((threadIdx.x&31)==0) sm[threadIdx.x>>5]=s;
    __syncthreads();
    if (threadIdx.x<8){
        s=sm[threadIdx.x];
        for (int o=4;o;o>>=1) s+=__shfl_down_sync(0xffu,s,o);
        if (threadIdx.x==0) g0[b*CC+c]=s*(1.f/NNp);
    }
}
__global__ void glob_kernel(const float* __restrict__ g0,
        const float* __restrict__ wg1,const float* __restrict__ bg1,
        const float* __restrict__ sg1,const float* __restrict__ tg1,
        const float* __restrict__ wg2,const float* __restrict__ bg2,
        const float* __restrict__ sg2,const float* __restrict__ tg2,
        float* __restrict__ g2){
    __shared__ float s0[128], s1[32];
    int b=blockIdx.x, t=threadIdx.x;
    s0[t]=g0[b*128+t]; __syncthreads();
    if (t<32){
        float a=0.f;
        for (int c=0;c<128;c++) a+=s0[c]*wg1[t*128+c];
        s1[t]=fmaxf(sg1[t]*(a+bg1[t])+tg1[t],0.f);
    }
    __syncthreads();
    float a=0.f;
    for (int i=0;i<32;i++) a+=s1[i]*wg2[t*32+i];
    g2[b*128+t]=sg2[t]*(a+bg2[t])+tg2[t];
}

// ---- h2 GEMM (K=384) + sigmoid epilogue -> final output ----
__global__ void __launch_bounds__(256) h2_gemm(const float* __restrict__ H,
        const float* __restrict__ Wl2, const float* __restrict__ bl2,
        const float* __restrict__ sl2, const float* __restrict__ tl2,
        const float* __restrict__ g2, float* __restrict__ out){
    __shared__ float As[16*TW], Bs[16*TW];
    int b=blockIdx.y, n0=blockIdx.x*128, tid=threadIdx.x;
    const float* Hb = H + ((size_t)b*NNp+n0)*384;
    int tr=tid>>4, tc=tid&15, r0=tr*4, c0=tc*4;
    ull acc[8][4];
#pragma unroll
    for(int i=0;i<8;i++)
#pragma unroll
        for(int j=0;j<4;j++) acc[i][j]=0ULL;
    for (int kk=0; kk<384; kk+=16){
        for (int i=tid;i<512;i+=256){             // Wl2[p][k] -> As[k][p]
            int m=i>>2, k4=(i&3)*4;
            float4 v = *(const float4*)(Wl2 + m*384 + kk + k4);
            As[(k4+0)*TW+m]=v.x; As[(k4+1)*TW+m]=v.y; As[(k4+2)*TW+m]=v.z; As[(k4+3)*TW+m]=v.w;
        }
        for (int i=tid;i<512;i+=256){             // H[n][k] -> Bs[k][n]
            int n=i>>2, k4=(i&3)*4;
            float4 v = *(const float4*)(Hb + (size_t)n*384 + kk + k4);
            Bs[(k4+0)*TW+n]=v.x; Bs[(k4+1)*TW+n]=v.y; Bs[(k4+2)*TW+n]=v.z; Bs[(k4+3)*TW+n]=v.w;
        }
        __syncthreads();
#pragma unroll
        for (int k=0;k<16;k++) micro_step(As,Bs,k,r0,c0,acc);
        __syncthreads();
    }
#pragma unroll
    for (int i=0;i<8;i++){
        int p=(i<4)? r0+i : r0+60+i;
        float bb=bl2[p], ss=sl2[p], tt=tl2[p], gg=g2[b*128+p];
        float* orow = out + ((size_t)b*CC+p)*NNp + n0;
#pragma unroll
        for (int j=0;j<4;j++){
            int cj=(j<2)? c0+2*j : c0+60+2*j;
            float2 v=unp(acc[i][j]);
            float l0=fmaxf(ss*(v.x+bb)+tt,0.f);
            float l1=fmaxf(ss*(v.y+bb)+tt,0.f);
            float2 o;
            o.x = 1.f/(1.f+__expf(-(gg+l0)));
            o.y = 1.f/(1.f+__expf(-(gg+l1)));
            *(float2*)(orow+cj)=o;
        }
    }
}

extern "C" void kernel_launch(void* const* d_in, const int* in_sizes, int n_in,
                              void* d_out, int out_size){
    const float* x    = (const float*)d_in[0];
    const float* w_be = (const float*)d_in[1];
    const float* b_be = (const float*)d_in[2];
    const float* s_be = (const float*)d_in[3];
    const float* t_be = (const float*)d_in[4];
    const float* w_kn = (const float*)d_in[5];
    const float* b_kn = (const float*)d_in[6];
    const float* s_kn = (const float*)d_in[7];
    const float* t_kn = (const float*)d_in[8];
    const float* w_g1 = (const float*)d_in[9];
    const float* b_g1 = (const float*)d_in[10];
    const float* s_g1 = (const float*)d_in[11];
    const float* t_g1 = (const float*)d_in[12];
    const float* w_g2 = (const float*)d_in[13];
    const float* b_g2 = (const float*)d_in[14];
    const float* s_g2 = (const float*)d_in[15];
    const float* t_g2 = (const float*)d_in[16];
    const float* w_l1 = (const float*)d_in[17];
    const float* b_l1 = (const float*)d_in[18];
    const float* s_l1 = (const float*)d_in[19];
    const float* t_l1 = (const float*)d_in[20];
    const float* w_l2 = (const float*)d_in[21];
    const float* b_l2 = (const float*)d_in[22];
    const float* s_l2 = (const float*)d_in[23];
    const float* t_l2 = (const float*)d_in[24];
    float* out = (float*)d_out;

    float *x1, *xf, *sq, *PC, *H, *g0, *g2, *W4, *Wl2; int* idx;
    cudaGetSymbolAddress((void**)&x1, g_x1);
    cudaGetSymbolAddress((void**)&xf, g_xf);
    cudaGetSymbolAddress((void**)&sq, g_sq);
    cudaGetSymbolAddress((void**)&idx, g_idx);
    cudaGetSymbolAddress((void**)&PC, g_PC);
    cudaGetSymbolAddress((void**)&H, g_h);
    cudaGetSymbolAddress((void**)&W4, g_W4);
    cudaGetSymbolAddress((void**)&Wl2, g_Wl2);
    cudaGetSymbolAddress((void**)&g0, g_g0);
    cudaGetSymbolAddress((void**)&g2, g_g2);

    const int knn_smem = (2*128*TW + 128) * 4;
    cudaFuncSetAttribute(knn_kernel, cudaFuncAttributeMaxDynamicSharedMemorySize, knn_smem);

    prep_kernel<<<256,256>>>(w_l1, w_l2);
    pw_gemm<<<dim3(32,BB),256>>>(x,  w_be, b_be, s_be, t_be, x1);
    pw_gemm<<<dim3(32,BB),256>>>(x1, w_kn, b_kn, s_kn, t_kn, xf);
    sq_kernel<<<dim3(16,BB),256>>>(xf, sq);
    knn_kernel<<<dim3(32,BB),256,knn_smem>>>(xf, sq, idx);
    pc_gemm<<<dim3(32,BB,4),256>>>(xf, W4, PC);
    gather_kernel<<<dim3(512,BB),256>>>(PC, idx, b_l1, s_l1, t_l1, H);
    mean_kernel<<<dim3(128,BB),256>>>(x1, g0);
    glob_kernel<<<BB,128>>>(g0, w_g1,b_g1,s_g1,t_g1, w_g2,b_g2,s_g2,t_g2, g2);
    h2_gemm<<<dim3(32,BB),256>>>(H, Wl2, b_l2, s_l2, t_l2, g2, out);
}